// round 1
// baseline (speedup 1.0000x reference)
#include <cuda_runtime.h>

#define NU_MAX 100000
#define NI_MAX 50000
#define EDIM 32

// ---------------- device scratch (static, no runtime allocation) ----------------
__device__ float g_FS[NU_MAX * EDIM];
__device__ float g_FD[NU_MAX * EDIM];
__device__ float g_H1[NI_MAX * EDIM];
__device__ float g_H2[NU_MAX * EDIM];
__device__ float g_A[NU_MAX * EDIM];
__device__ float g_B[NU_MAX * EDIM];
__device__ float g_S1[NI_MAX];
__device__ float g_S2[NU_MAX];
__device__ float g_S3[NU_MAX];
__device__ float g_S4[NU_MAX];
__device__ float g_stats[64];

// ---------------- zero scratch ----------------
__global__ void zero_all_kernel(int nu, int ni) {
    long i0 = (long)blockIdx.x * blockDim.x + threadIdx.x;
    long stride = (long)gridDim.x * blockDim.x;
    long nuE = (long)nu * EDIM, niE = (long)ni * EDIM;
    for (long i = i0; i < nuE; i += stride) { g_H2[i] = 0.f; g_A[i] = 0.f; g_B[i] = 0.f; }
    for (long i = i0; i < niE; i += stride) g_H1[i] = 0.f;
    for (long i = i0; i < nu;  i += stride) { g_S2[i] = 0.f; g_S3[i] = 0.f; g_S4[i] = 0.f; }
    for (long i = i0; i < ni;  i += stride) g_S1[i] = 0.f;
    if (i0 < 64) g_stats[i0] = 0.f;
}

// ---------------- node projection: out[r,c] = (in[r,:]*scale(r)) . W[c,:] + bias[c] ----
// scale(r) = 1/sdenom[r] (0 if sdenom==0) when sdenom != nullptr (folds GAT normalization)
__global__ void proj_kernel(const float* __restrict__ in, const float* __restrict__ W,
                            const float* __restrict__ bias, const float* __restrict__ sdenom,
                            float* __restrict__ out, int nrows) {
    __shared__ float Wsh[32 * 33];
    int tid = threadIdx.x;
    for (int i = tid; i < 32 * 32; i += blockDim.x)
        Wsh[(i >> 5) * 33 + (i & 31)] = W[i];
    __syncthreads();
    int warp = tid >> 5, lane = tid & 31;
    int row = blockIdx.x * 8 + warp;
    if (row >= nrows) return;
    float scale = 1.0f;
    if (sdenom) {
        float sv = sdenom[row];
        scale = (sv > 0.f) ? (1.0f / sv) : 0.0f;
    }
    float h = in[row * 32 + lane] * scale;
    float acc = bias[lane];
#pragma unroll
    for (int k = 0; k < 32; ++k) {
        float hk = __shfl_sync(0xffffffffu, h, k);
        acc += hk * Wsh[lane * 33 + k];
    }
    out[row * 32 + lane] = acc;
}

// ---------------- fused GATv2 edge pass (one pass, no max-subtraction needed) ------
// out[dst] += exp(e) * fs[src] ; sdenom[dst] += exp(e)
// e = attn . leaky_relu(fs[src] + fd[dst], 0.2)
__global__ void edge_kernel(const int* __restrict__ src, const int* __restrict__ dst,
                            const float* __restrict__ fs, const float* __restrict__ fd,
                            const float* __restrict__ attn,
                            float* __restrict__ out, float* __restrict__ sdenom, int ne) {
    int lane = threadIdx.x & 31;
    int e = (int)(((long)blockIdx.x * blockDim.x + threadIdx.x) >> 5);
    if (e >= ne) return;
    int si = src[e];
    int di = dst[e];
    float fsv = __ldg(&fs[si * 32 + lane]);
    float fdv = __ldg(&fd[di * 32 + lane]);
    float t = fsv + fdv;
    t = (t > 0.f) ? t : 0.2f * t;
    float v = t * __ldg(&attn[lane]);
#pragma unroll
    for (int o = 16; o; o >>= 1) v += __shfl_xor_sync(0xffffffffu, v, o);
    float ex = __expf(v);
    atomicAdd(&out[di * 32 + lane], ex * fsv);
    if (lane == 0) atomicAdd(&sdenom[di], ex);
}

// ---------------- output head: y = [A/s3, B/s4] @ Wout^T + bout --------------------
__global__ void head_kernel(const float* __restrict__ A, const float* __restrict__ B,
                            const float* __restrict__ s3, const float* __restrict__ s4,
                            const float* __restrict__ Wout, const float* __restrict__ bout,
                            float* __restrict__ y, int nu) {
    __shared__ float Wsh[32 * 65];
    int tid = threadIdx.x;
    for (int i = tid; i < 32 * 64; i += blockDim.x)
        Wsh[(i >> 6) * 65 + (i & 63)] = Wout[i];
    __syncthreads();
    int warp = tid >> 5, lane = tid & 31;
    int row = blockIdx.x * 8 + warp;
    if (row >= nu) return;
    float sa = s3[row]; sa = (sa > 0.f) ? (1.0f / sa) : 0.0f;
    float sb = s4[row]; sb = (sb > 0.f) ? (1.0f / sb) : 0.0f;
    float av = A[row * 32 + lane] * sa;
    float bv = B[row * 32 + lane] * sb;
    float acc = bout[lane];
#pragma unroll
    for (int k = 0; k < 32; ++k) {
        float ak = __shfl_sync(0xffffffffu, av, k);
        float bk = __shfl_sync(0xffffffffu, bv, k);
        acc += ak * Wsh[lane * 65 + k] + bk * Wsh[lane * 65 + 32 + k];
    }
    y[row * 32 + lane] = acc;
}

// ---------------- batchnorm stats (per-column sum & sumsq over nu rows) ------------
__global__ void stats_kernel(const float* __restrict__ y, int nu) {
    int lane = threadIdx.x & 31;
    long total = (long)nu * 32;
    long stride = (long)gridDim.x * blockDim.x;   // multiple of 32 -> lane == column
    float sum = 0.f, sq = 0.f;
    for (long i = (long)blockIdx.x * blockDim.x + threadIdx.x; i < total; i += stride) {
        float v = y[i];
        sum += v;
        sq += v * v;
    }
    __shared__ float ssum[32], ssq[32];
    if (threadIdx.x < 32) { ssum[threadIdx.x] = 0.f; ssq[threadIdx.x] = 0.f; }
    __syncthreads();
    atomicAdd(&ssum[lane], sum);
    atomicAdd(&ssq[lane], sq);
    __syncthreads();
    if (threadIdx.x < 32) {
        atomicAdd(&g_stats[lane], ssum[lane]);
        atomicAdd(&g_stats[32 + lane], ssq[lane]);
    }
}

// ---------------- finalize: BN(training stats) + LeakyReLU(0.01), in-place ---------
__global__ void finalize_kernel(float* __restrict__ y, const float* __restrict__ gamma,
                                const float* __restrict__ beta, int nu) {
    int i = blockIdx.x * blockDim.x + threadIdx.x;
    if (i >= nu * 32) return;
    int c = i & 31;
    float inv_n = 1.0f / (float)nu;
    float mean = g_stats[c] * inv_n;
    float var = g_stats[32 + c] * inv_n - mean * mean;
    float v = (y[i] - mean) * rsqrtf(var + 1e-5f) * gamma[c] + beta[c];
    y[i] = (v > 0.f) ? v : 0.01f * v;
}

// ---------------- host launch ----------------
extern "C" void kernel_launch(void* const* d_in, const int* in_sizes, int n_in,
                              void* d_out, int out_size) {
    const float* user = (const float*)d_in[0];
    const float* item = (const float*)d_in[1];
    const int* rate_src  = (const int*)d_in[2];
    const int* rate_dst  = (const int*)d_in[3];
    const int* trust_src = (const int*)d_in[4];
    const int* trust_dst = (const int*)d_in[5];
    // 4 relations * (Wsrc, bsrc, Wdst, bdst, attn) at indices 6..25
    const float* p[20];
    for (int i = 0; i < 20; ++i) p[i] = (const float*)d_in[6 + i];
    const float* Wout  = (const float*)d_in[26];
    const float* bout  = (const float*)d_in[27];
    const float* gamma = (const float*)d_in[28];
    const float* beta  = (const float*)d_in[29];

    int nu = in_sizes[0] / EDIM;
    int ni = in_sizes[1] / EDIM;
    int ne_rate  = in_sizes[2];
    int ne_trust = in_sizes[4];
    float* y = (float*)d_out;

    float *FS, *FD, *H1, *H2, *A, *B, *S1, *S2, *S3, *S4;
    cudaGetSymbolAddress((void**)&FS, g_FS);
    cudaGetSymbolAddress((void**)&FD, g_FD);
    cudaGetSymbolAddress((void**)&H1, g_H1);
    cudaGetSymbolAddress((void**)&H2, g_H2);
    cudaGetSymbolAddress((void**)&A,  g_A);
    cudaGetSymbolAddress((void**)&B,  g_B);
    cudaGetSymbolAddress((void**)&S1, g_S1);
    cudaGetSymbolAddress((void**)&S2, g_S2);
    cudaGetSymbolAddress((void**)&S3, g_S3);
    cudaGetSymbolAddress((void**)&S4, g_S4);

    const int T = 256;
    int gu = (nu + 7) / 8;
    int gi = (ni + 7) / 8;
    int ge_rate  = (ne_rate + 7) / 8;
    int ge_trust = (ne_trust + 7) / 8;

    zero_all_kernel<<<2048, T>>>(nu, ni);

    // layer 1, 'rate': user -> item
    proj_kernel<<<gu, T>>>(user, p[0], p[1], nullptr, FS, nu);
    proj_kernel<<<gi, T>>>(item, p[2], p[3], nullptr, FD, ni);
    edge_kernel<<<ge_rate, T>>>(rate_src, rate_dst, FS, FD, p[4], H1, S1, ne_rate);

    // layer 1, 'rated-by': item -> user
    proj_kernel<<<gi, T>>>(item, p[5], p[6], nullptr, FS, ni);
    proj_kernel<<<gu, T>>>(user, p[7], p[8], nullptr, FD, nu);
    edge_kernel<<<ge_rate, T>>>(rate_dst, rate_src, FS, FD, p[9], H2, S2, ne_rate);

    // layer 2, 'rated-by' on h1 (normalization of H1 folded into projection via S1)
    proj_kernel<<<gi, T>>>(H1, p[10], p[11], S1, FS, ni);
    proj_kernel<<<gu, T>>>(user, p[12], p[13], nullptr, FD, nu);
    edge_kernel<<<ge_rate, T>>>(rate_dst, rate_src, FS, FD, p[14], A, S3, ne_rate);

    // layer 2, 'trust' on h2 (normalization of H2 folded via S2)
    proj_kernel<<<gu, T>>>(H2, p[15], p[16], S2, FS, nu);
    proj_kernel<<<gu, T>>>(user, p[17], p[18], nullptr, FD, nu);
    edge_kernel<<<ge_trust, T>>>(trust_src, trust_dst, FS, FD, p[19], B, S4, ne_trust);

    // head + batchnorm + leakyrelu (A/B normalization folded via S3/S4)
    head_kernel<<<gu, T>>>(A, B, S3, S4, Wout, bout, y, nu);
    stats_kernel<<<1024, T>>>(y, nu);
    finalize_kernel<<<(nu * EDIM + T - 1) / T, T>>>(y, gamma, beta, nu);
}

// round 2
// speedup vs baseline: 1.5543x; 1.5543x over previous
#include <cuda_runtime.h>

#define NU_MAX 100000
#define NI_MAX 50000
#define EDIM 32

// ---------------- device scratch (static, 16B-aligned for float4 access) ----------
__device__ __align__(256) float g_FS [NU_MAX * EDIM];
__device__ __align__(256) float g_FD [NU_MAX * EDIM];
__device__ __align__(256) float g_FS2[NU_MAX * EDIM];
__device__ __align__(256) float g_FD2[NU_MAX * EDIM];
__device__ __align__(256) float g_H1 [NI_MAX * EDIM];
__device__ __align__(256) float g_H2 [NU_MAX * EDIM];
__device__ __align__(256) float g_A  [NU_MAX * EDIM];
__device__ __align__(256) float g_B  [NU_MAX * EDIM];
__device__ float g_S1[NI_MAX];
__device__ float g_S2[NU_MAX];
__device__ float g_S3[NU_MAX];
__device__ float g_S4[NU_MAX];
__device__ float g_stats[64];

__device__ __forceinline__ void red_add_v4(float* p, float4 v) {
    asm volatile("red.global.add.v4.f32 [%0], {%1,%2,%3,%4};"
                 :: "l"(p), "f"(v.x), "f"(v.y), "f"(v.z), "f"(v.w) : "memory");
}
__device__ __forceinline__ float lrelu02(float t) { return t > 0.f ? t : 0.2f * t; }

// ---------------- zero scratch ----------------
__global__ void zero_all_kernel(int nu, int ni) {
    long i0 = (long)blockIdx.x * blockDim.x + threadIdx.x;
    long stride = (long)gridDim.x * blockDim.x;
    long nuE = (long)nu * EDIM, niE = (long)ni * EDIM;
    for (long i = i0; i < nuE; i += stride) { g_H2[i] = 0.f; g_A[i] = 0.f; g_B[i] = 0.f; }
    for (long i = i0; i < niE; i += stride) g_H1[i] = 0.f;
    for (long i = i0; i < nu;  i += stride) { g_S2[i] = 0.f; g_S3[i] = 0.f; g_S4[i] = 0.f; }
    for (long i = i0; i < ni;  i += stride) g_S1[i] = 0.f;
    if (i0 < 64) g_stats[i0] = 0.f;
}

// ---------------- node projection ----------------
__global__ void proj_kernel(const float* __restrict__ in, const float* __restrict__ W,
                            const float* __restrict__ bias, const float* __restrict__ sdenom,
                            float* __restrict__ out, int nrows) {
    __shared__ float Wsh[32 * 33];
    int tid = threadIdx.x;
    for (int i = tid; i < 32 * 32; i += blockDim.x)
        Wsh[(i >> 5) * 33 + (i & 31)] = W[i];
    __syncthreads();
    int warp = tid >> 5, lane = tid & 31;
    int row = blockIdx.x * 8 + warp;
    if (row >= nrows) return;
    float scale = 1.0f;
    if (sdenom) {
        float sv = sdenom[row];
        scale = (sv > 0.f) ? (1.0f / sv) : 0.0f;
    }
    float h = in[row * 32 + lane] * scale;
    float acc = bias[lane];
#pragma unroll
    for (int k = 0; k < 32; ++k) {
        float hk = __shfl_sync(0xffffffffu, h, k);
        acc += hk * Wsh[lane * 33 + k];
    }
    out[row * 32 + lane] = acc;
}

// ---------------- core edge step: 8 lanes per edge, float4 channels ----------------
__device__ __forceinline__ void edge_step(
    int si, int di, int q, bool valid,
    const float4* __restrict__ fs, const float4* __restrict__ fd,
    const float4* __restrict__ attn, float* __restrict__ out, float* __restrict__ den)
{
    float4 fsv = __ldg(&fs[si * 8 + q]);
    float4 fdv = __ldg(&fd[di * 8 + q]);
    float4 a = __ldg(&attn[q]);
    float s = lrelu02(fsv.x + fdv.x) * a.x + lrelu02(fsv.y + fdv.y) * a.y
            + lrelu02(fsv.z + fdv.z) * a.z + lrelu02(fsv.w + fdv.w) * a.w;
    s += __shfl_xor_sync(0xffffffffu, s, 1);
    s += __shfl_xor_sync(0xffffffffu, s, 2);
    s += __shfl_xor_sync(0xffffffffu, s, 4);
    float ex = __expf(s);
    if (valid) {
        float4 r = make_float4(ex * fsv.x, ex * fsv.y, ex * fsv.z, ex * fsv.w);
        red_add_v4(&out[di * 32 + q * 4], r);
        if (q == 0) atomicAdd(&den[di], ex);
    }
}

// ---------------- layer-1 fused: both directions over the 'rate' edge list ---------
__global__ void edge_l1_kernel(const int* __restrict__ src, const int* __restrict__ dst,
                               const float4* __restrict__ fsA, const float4* __restrict__ fdA,
                               const float4* __restrict__ attnA, float* __restrict__ outA, float* __restrict__ denA,
                               const float4* __restrict__ fsB, const float4* __restrict__ fdB,
                               const float4* __restrict__ attnB, float* __restrict__ outB, float* __restrict__ denB,
                               int ne) {
    int t = blockIdx.x * blockDim.x + threadIdx.x;
    int e = t >> 3;
    int q = t & 7;
    bool valid = e < ne;
    int ec = valid ? e : ne - 1;
    int u = __ldg(&src[ec]);
    int v = __ldg(&dst[ec]);
    edge_step(u, v, q, valid, fsA, fdA, attnA, outA, denA);   // u -> v ('rate')
    edge_step(v, u, q, valid, fsB, fdB, attnB, outB, denB);   // v -> u ('rated-by')
}

// ---------------- layer-2 dual: two independent edge lists in one grid --------------
__global__ void edge_l2_kernel(
    const int* __restrict__ s1, const int* __restrict__ d1,
    const float4* __restrict__ fs1, const float4* __restrict__ fd1,
    const float4* __restrict__ a1, float* __restrict__ o1, float* __restrict__ den1,
    int ne1, int nb1,
    const int* __restrict__ s2, const int* __restrict__ d2,
    const float4* __restrict__ fs2, const float4* __restrict__ fd2,
    const float4* __restrict__ a2, float* __restrict__ o2, float* __restrict__ den2,
    int ne2)
{
    bool second = (int)blockIdx.x >= nb1;
    int b = second ? (int)blockIdx.x - nb1 : (int)blockIdx.x;
    const int* src = second ? s2 : s1;
    const int* dst = second ? d2 : d1;
    const float4* fs = second ? fs2 : fs1;
    const float4* fd = second ? fd2 : fd1;
    const float4* at = second ? a2 : a1;
    float* out = second ? o2 : o1;
    float* den = second ? den2 : den1;
    int ne = second ? ne2 : ne1;

    int t = b * blockDim.x + threadIdx.x;
    int e = t >> 3;
    int q = t & 7;
    bool valid = e < ne;
    int ec = valid ? e : ne - 1;
    int u = __ldg(&src[ec]);
    int v = __ldg(&dst[ec]);
    edge_step(u, v, q, valid, fs, fd, at, out, den);
}

// ---------------- output head ----------------
__global__ void head_kernel(const float* __restrict__ A, const float* __restrict__ B,
                            const float* __restrict__ s3, const float* __restrict__ s4,
                            const float* __restrict__ Wout, const float* __restrict__ bout,
                            float* __restrict__ y, int nu) {
    __shared__ float Wsh[32 * 65];
    int tid = threadIdx.x;
    for (int i = tid; i < 32 * 64; i += blockDim.x)
        Wsh[(i >> 6) * 65 + (i & 63)] = Wout[i];
    __syncthreads();
    int warp = tid >> 5, lane = tid & 31;
    int row = blockIdx.x * 8 + warp;
    if (row >= nu) return;
    float sa = s3[row]; sa = (sa > 0.f) ? (1.0f / sa) : 0.0f;
    float sb = s4[row]; sb = (sb > 0.f) ? (1.0f / sb) : 0.0f;
    float av = A[row * 32 + lane] * sa;
    float bv = B[row * 32 + lane] * sb;
    float acc = bout[lane];
#pragma unroll
    for (int k = 0; k < 32; ++k) {
        float ak = __shfl_sync(0xffffffffu, av, k);
        float bk = __shfl_sync(0xffffffffu, bv, k);
        acc += ak * Wsh[lane * 65 + k] + bk * Wsh[lane * 65 + 32 + k];
    }
    y[row * 32 + lane] = acc;
}

// ---------------- batchnorm stats ----------------
__global__ void stats_kernel(const float* __restrict__ y, int nu) {
    int lane = threadIdx.x & 31;
    long total = (long)nu * 32;
    long stride = (long)gridDim.x * blockDim.x;
    float sum = 0.f, sq = 0.f;
    for (long i = (long)blockIdx.x * blockDim.x + threadIdx.x; i < total; i += stride) {
        float v = y[i];
        sum += v;
        sq += v * v;
    }
    __shared__ float ssum[32], ssq[32];
    if (threadIdx.x < 32) { ssum[threadIdx.x] = 0.f; ssq[threadIdx.x] = 0.f; }
    __syncthreads();
    atomicAdd(&ssum[lane], sum);
    atomicAdd(&ssq[lane], sq);
    __syncthreads();
    if (threadIdx.x < 32) {
        atomicAdd(&g_stats[lane], ssum[lane]);
        atomicAdd(&g_stats[32 + lane], ssq[lane]);
    }
}

// ---------------- finalize: BN + LeakyReLU(0.01) ----------------
__global__ void finalize_kernel(float* __restrict__ y, const float* __restrict__ gamma,
                                const float* __restrict__ beta, int nu) {
    int i = blockIdx.x * blockDim.x + threadIdx.x;
    if (i >= nu * 32) return;
    int c = i & 31;
    float inv_n = 1.0f / (float)nu;
    float mean = g_stats[c] * inv_n;
    float var = g_stats[32 + c] * inv_n - mean * mean;
    float v = (y[i] - mean) * rsqrtf(var + 1e-5f) * gamma[c] + beta[c];
    y[i] = (v > 0.f) ? v : 0.01f * v;
}

// ---------------- host launch ----------------
extern "C" void kernel_launch(void* const* d_in, const int* in_sizes, int n_in,
                              void* d_out, int out_size) {
    const float* user = (const float*)d_in[0];
    const float* item = (const float*)d_in[1];
    const int* rate_src  = (const int*)d_in[2];
    const int* rate_dst  = (const int*)d_in[3];
    const int* trust_src = (const int*)d_in[4];
    const int* trust_dst = (const int*)d_in[5];
    const float* p[20];
    for (int i = 0; i < 20; ++i) p[i] = (const float*)d_in[6 + i];
    const float* Wout  = (const float*)d_in[26];
    const float* bout  = (const float*)d_in[27];
    const float* gamma = (const float*)d_in[28];
    const float* beta  = (const float*)d_in[29];

    int nu = in_sizes[0] / EDIM;
    int ni = in_sizes[1] / EDIM;
    int ne_rate  = in_sizes[2];
    int ne_trust = in_sizes[4];
    float* y = (float*)d_out;

    float *FS, *FD, *FS2, *FD2, *H1, *H2, *A, *B, *S1, *S2, *S3, *S4;
    cudaGetSymbolAddress((void**)&FS,  g_FS);
    cudaGetSymbolAddress((void**)&FD,  g_FD);
    cudaGetSymbolAddress((void**)&FS2, g_FS2);
    cudaGetSymbolAddress((void**)&FD2, g_FD2);
    cudaGetSymbolAddress((void**)&H1,  g_H1);
    cudaGetSymbolAddress((void**)&H2,  g_H2);
    cudaGetSymbolAddress((void**)&A,   g_A);
    cudaGetSymbolAddress((void**)&B,   g_B);
    cudaGetSymbolAddress((void**)&S1,  g_S1);
    cudaGetSymbolAddress((void**)&S2,  g_S2);
    cudaGetSymbolAddress((void**)&S3,  g_S3);
    cudaGetSymbolAddress((void**)&S4,  g_S4);

    const int T = 256;
    int gu = (nu + 7) / 8;
    int gi = (ni + 7) / 8;
    // 8 lanes per edge -> 32 edges per 256-thread block
    int gb_rate  = (ne_rate  * 8 + T - 1) / T;
    int gb_trust = (ne_trust * 8 + T - 1) / T;

    zero_all_kernel<<<2048, T>>>(nu, ni);

    // layer 1 projections (both directions of the rate graph)
    proj_kernel<<<gu, T>>>(user, p[0], p[1], nullptr, FS,  nu);   // l1_rate  Wsrc (user)
    proj_kernel<<<gi, T>>>(item, p[2], p[3], nullptr, FD,  ni);   // l1_rate  Wdst (item)
    proj_kernel<<<gi, T>>>(item, p[5], p[6], nullptr, FS2, ni);   // l1_rby   Wsrc (item)
    proj_kernel<<<gu, T>>>(user, p[7], p[8], nullptr, FD2, nu);   // l1_rby   Wdst (user)

    // layer 1 fused edge pass (rate + rated-by share the edge list)
    edge_l1_kernel<<<gb_rate, T>>>(rate_src, rate_dst,
                                   (const float4*)FS,  (const float4*)FD,  (const float4*)p[4], H1, S1,
                                   (const float4*)FS2, (const float4*)FD2, (const float4*)p[9], H2, S2,
                                   ne_rate);

    // layer 2 projections (normalization folded via S1/S2)
    proj_kernel<<<gi, T>>>(H1,   p[10], p[11], S1,      FS,  ni);  // l2_rby   Wsrc (h1)
    proj_kernel<<<gu, T>>>(user, p[12], p[13], nullptr, FD,  nu);  // l2_rby   Wdst (user)
    proj_kernel<<<gu, T>>>(H2,   p[15], p[16], S2,      FS2, nu);  // l2_trust Wsrc (h2)
    proj_kernel<<<gu, T>>>(user, p[17], p[18], nullptr, FD2, nu);  // l2_trust Wdst (user)

    // layer 2 dual edge pass (rby over rate list reversed + trust list), one grid
    edge_l2_kernel<<<gb_rate + gb_trust, T>>>(
        rate_dst, rate_src, (const float4*)FS, (const float4*)FD, (const float4*)p[14], A, S3,
        ne_rate, gb_rate,
        trust_src, trust_dst, (const float4*)FS2, (const float4*)FD2, (const float4*)p[19], B, S4,
        ne_trust);

    // head + batchnorm + leakyrelu
    head_kernel<<<gu, T>>>(A, B, S3, S4, Wout, bout, y, nu);
    stats_kernel<<<1024, T>>>(y, nu);
    finalize_kernel<<<(nu * EDIM + T - 1) / T, T>>>(y, gamma, beta, nu);
}

// round 4
// speedup vs baseline: 1.6800x; 1.0809x over previous
#include <cuda_runtime.h>

#define NU_MAX 100000
#define NI_MAX 50000
#define EDIM 32

// ---------------- device scratch ----------------
__device__ __align__(256) float g_U0[NU_MAX * EDIM];
__device__ __align__(256) float g_U1[NU_MAX * EDIM];
__device__ __align__(256) float g_U2[NU_MAX * EDIM];
__device__ __align__(256) float g_U3[NU_MAX * EDIM];
__device__ __align__(256) float g_I0[NI_MAX * EDIM];
__device__ __align__(256) float g_I1[NI_MAX * EDIM];
__device__ __align__(256) float g_P1[NI_MAX * EDIM];
__device__ __align__(256) float g_P2[NU_MAX * EDIM];
__device__ __align__(256) float g_H1[NI_MAX * EDIM];
__device__ __align__(256) float g_H2[NU_MAX * EDIM];
__device__ __align__(256) float g_A [NU_MAX * EDIM];
__device__ __align__(256) float g_B [NU_MAX * EDIM];
__device__ float g_S1[NI_MAX];
__device__ float g_S2[NU_MAX];
__device__ float g_S3[NU_MAX];
__device__ float g_S4[NU_MAX];
__device__ float g_stats[64];

__device__ __forceinline__ void red_add_v4(float* p, float4 v) {
    asm volatile("red.global.add.v4.f32 [%0], {%1,%2,%3,%4};"
                 :: "l"(p), "f"(v.x), "f"(v.y), "f"(v.z), "f"(v.w) : "memory");
}
__device__ __forceinline__ float lrelu02(float t) { return t > 0.f ? t : 0.2f * t; }

// ---------------- zero scratch ----------------
__global__ void zero_all_kernel(int nu, int ni) {
    long i0 = (long)blockIdx.x * blockDim.x + threadIdx.x;
    long stride = (long)gridDim.x * blockDim.x;
    long nuE = (long)nu * EDIM, niE = (long)ni * EDIM;
    for (long i = i0; i < nuE; i += stride) { g_H2[i] = 0.f; g_A[i] = 0.f; g_B[i] = 0.f; }
    for (long i = i0; i < niE; i += stride) g_H1[i] = 0.f;
    for (long i = i0; i < nu;  i += stride) { g_S2[i] = 0.f; g_S3[i] = 0.f; g_S4[i] = 0.f; }
    for (long i = i0; i < ni;  i += stride) g_S1[i] = 0.f;
    if (i0 < 64) g_stats[i0] = 0.f;
}

// ---------------- quad projection: one input, four weight matrices ----------------
// out_m[r, c] = in[r, :] . Wm[c, :] + bm[c]
__global__ void proj4_kernel(const float* __restrict__ in,
                             const float* __restrict__ W0, const float* __restrict__ b0,
                             const float* __restrict__ W1, const float* __restrict__ b1,
                             const float* __restrict__ W2, const float* __restrict__ b2,
                             const float* __restrict__ W3, const float* __restrict__ b3,
                             float* __restrict__ O0, float* __restrict__ O1,
                             float* __restrict__ O2, float* __restrict__ O3, int nrows) {
    __shared__ float Wsh[4][32 * 36];
    int tid = threadIdx.x;
    const float* Ws[4] = {W0, W1, W2, W3};
    for (int i = tid; i < 4 * 1024; i += blockDim.x) {
        int m = i >> 10, r = (i >> 5) & 31, c = i & 31;
        Wsh[m][r * 36 + c] = Ws[m][r * 32 + c];
    }
    __syncthreads();
    int warp = tid >> 5, lane = tid & 31;
    int row = blockIdx.x * 8 + warp;
    if (row >= nrows) return;
    float h = in[row * 32 + lane];
    float a0 = b0[lane], a1 = b1[lane], a2 = b2[lane], a3 = b3[lane];
#pragma unroll
    for (int k = 0; k < 32; k += 4) {
        float h0 = __shfl_sync(0xffffffffu, h, k);
        float h1 = __shfl_sync(0xffffffffu, h, k + 1);
        float h2 = __shfl_sync(0xffffffffu, h, k + 2);
        float h3 = __shfl_sync(0xffffffffu, h, k + 3);
        float4 w;
        w = *(const float4*)&Wsh[0][lane * 36 + k]; a0 += h0 * w.x + h1 * w.y + h2 * w.z + h3 * w.w;
        w = *(const float4*)&Wsh[1][lane * 36 + k]; a1 += h0 * w.x + h1 * w.y + h2 * w.z + h3 * w.w;
        w = *(const float4*)&Wsh[2][lane * 36 + k]; a2 += h0 * w.x + h1 * w.y + h2 * w.z + h3 * w.w;
        w = *(const float4*)&Wsh[3][lane * 36 + k]; a3 += h0 * w.x + h1 * w.y + h2 * w.z + h3 * w.w;
    }
    O0[row * 32 + lane] = a0;
    O1[row * 32 + lane] = a1;
    O2[row * 32 + lane] = a2;
    O3[row * 32 + lane] = a3;
}

// ---------------- dual projection: one input, two weight matrices ----------------
__global__ void proj2_kernel(const float* __restrict__ in,
                             const float* __restrict__ W0, const float* __restrict__ b0,
                             const float* __restrict__ W1, const float* __restrict__ b1,
                             float* __restrict__ O0, float* __restrict__ O1, int nrows) {
    __shared__ float Wsh[2][32 * 36];
    int tid = threadIdx.x;
    const float* Ws[2] = {W0, W1};
    for (int i = tid; i < 2 * 1024; i += blockDim.x) {
        int m = i >> 10, r = (i >> 5) & 31, c = i & 31;
        Wsh[m][r * 36 + c] = Ws[m][r * 32 + c];
    }
    __syncthreads();
    int warp = tid >> 5, lane = tid & 31;
    int row = blockIdx.x * 8 + warp;
    if (row >= nrows) return;
    float h = in[row * 32 + lane];
    float a0 = b0[lane], a1 = b1[lane];
#pragma unroll
    for (int k = 0; k < 32; k += 4) {
        float h0 = __shfl_sync(0xffffffffu, h, k);
        float h1 = __shfl_sync(0xffffffffu, h, k + 1);
        float h2 = __shfl_sync(0xffffffffu, h, k + 2);
        float h3 = __shfl_sync(0xffffffffu, h, k + 3);
        float4 w;
        w = *(const float4*)&Wsh[0][lane * 36 + k]; a0 += h0 * w.x + h1 * w.y + h2 * w.z + h3 * w.w;
        w = *(const float4*)&Wsh[1][lane * 36 + k]; a1 += h0 * w.x + h1 * w.y + h2 * w.z + h3 * w.w;
    }
    O0[row * 32 + lane] = a0;
    O1[row * 32 + lane] = a1;
}

// ---------------- H1/H2 projection (scaled by 1/S), two segments in one grid ------
__global__ void projHH_kernel(const float* __restrict__ inA, const float* __restrict__ sA,
                              const float* __restrict__ WA, const float* __restrict__ bA,
                              float* __restrict__ OA, int nA, int nbA,
                              const float* __restrict__ inB, const float* __restrict__ sB,
                              const float* __restrict__ WB, const float* __restrict__ bB,
                              float* __restrict__ OB, int nB) {
    bool second = (int)blockIdx.x >= nbA;
    int b = second ? (int)blockIdx.x - nbA : (int)blockIdx.x;
    const float* in = second ? inB : inA;
    const float* sd = second ? sB : sA;
    const float* W  = second ? WB : WA;
    const float* bi = second ? bB : bA;
    float* out = second ? OB : OA;
    int nrows = second ? nB : nA;

    __shared__ float Wsh[32 * 36];
    int tid = threadIdx.x;
    for (int i = tid; i < 1024; i += blockDim.x)
        Wsh[(i >> 5) * 36 + (i & 31)] = W[i];
    __syncthreads();
    int warp = tid >> 5, lane = tid & 31;
    int row = b * 8 + warp;
    if (row >= nrows) return;
    float sv = sd[row];
    float scale = (sv > 0.f) ? (1.0f / sv) : 0.0f;
    float h = in[row * 32 + lane] * scale;
    float acc = bi[lane];
#pragma unroll
    for (int k = 0; k < 32; k += 4) {
        float h0 = __shfl_sync(0xffffffffu, h, k);
        float h1 = __shfl_sync(0xffffffffu, h, k + 1);
        float h2 = __shfl_sync(0xffffffffu, h, k + 2);
        float h3 = __shfl_sync(0xffffffffu, h, k + 3);
        float4 w = *(const float4*)&Wsh[lane * 36 + k];
        acc += h0 * w.x + h1 * w.y + h2 * w.z + h3 * w.w;
    }
    out[row * 32 + lane] = acc;
}

// ---------------- core edge step: 8 lanes per edge, float4 channels ----------------
__device__ __forceinline__ void edge_step(
    int si, int di, int q, bool valid,
    const float4* __restrict__ fs, const float4* __restrict__ fd,
    const float4* __restrict__ attn, float* __restrict__ out, float* __restrict__ den)
{
    float4 fsv = __ldg(&fs[si * 8 + q]);
    float4 fdv = __ldg(&fd[di * 8 + q]);
    float4 a = __ldg(&attn[q]);
    float s = lrelu02(fsv.x + fdv.x) * a.x + lrelu02(fsv.y + fdv.y) * a.y
            + lrelu02(fsv.z + fdv.z) * a.z + lrelu02(fsv.w + fdv.w) * a.w;
    s += __shfl_xor_sync(0xffffffffu, s, 1);
    s += __shfl_xor_sync(0xffffffffu, s, 2);
    s += __shfl_xor_sync(0xffffffffu, s, 4);
    float ex = __expf(s);
    if (valid) {
        float4 r = make_float4(ex * fsv.x, ex * fsv.y, ex * fsv.z, ex * fsv.w);
        red_add_v4(&out[di * 32 + q * 4], r);
        if (q == 0) atomicAdd(&den[di], ex);
    }
}

// ---------------- layer-1 fused: both directions over the 'rate' edge list ---------
__global__ void edge_l1_kernel(const int* __restrict__ src, const int* __restrict__ dst,
                               const float4* __restrict__ fsA, const float4* __restrict__ fdA,
                               const float4* __restrict__ attnA, float* __restrict__ outA, float* __restrict__ denA,
                               const float4* __restrict__ fsB, const float4* __restrict__ fdB,
                               const float4* __restrict__ attnB, float* __restrict__ outB, float* __restrict__ denB,
                               int ne) {
    int t = blockIdx.x * blockDim.x + threadIdx.x;
    int e = t >> 3;
    int q = t & 7;
    bool valid = e < ne;
    int ec = valid ? e : ne - 1;
    int u = __ldg(&src[ec]);
    int v = __ldg(&dst[ec]);
    edge_step(u, v, q, valid, fsA, fdA, attnA, outA, denA);   // user u -> item v ('rate')
    edge_step(v, u, q, valid, fsB, fdB, attnB, outB, denB);   // item v -> user u ('rated-by')
}

// ---------------- layer-2 dual: two independent edge lists in one grid --------------
__global__ void edge_l2_kernel(
    const int* __restrict__ s1, const int* __restrict__ d1,
    const float4* __restrict__ fs1, const float4* __restrict__ fd1,
    const float4* __restrict__ a1, float* __restrict__ o1, float* __restrict__ den1,
    int ne1, int nb1,
    const int* __restrict__ s2, const int* __restrict__ d2,
    const float4* __restrict__ fs2, const float4* __restrict__ fd2,
    const float4* __restrict__ a2, float* __restrict__ o2, float* __restrict__ den2,
    int ne2)
{
    bool second = (int)blockIdx.x >= nb1;
    int b = second ? (int)blockIdx.x - nb1 : (int)blockIdx.x;
    const int* src = second ? s2 : s1;
    const int* dst = second ? d2 : d1;
    const float4* fs = second ? fs2 : fs1;
    const float4* fd = second ? fd2 : fd1;
    const float4* at = second ? a2 : a1;
    float* out = second ? o2 : o1;
    float* den = second ? den2 : den1;
    int ne = second ? ne2 : ne1;

    int t = b * blockDim.x + threadIdx.x;
    int e = t >> 3;
    int q = t & 7;
    bool valid = e < ne;
    int ec = valid ? e : ne - 1;
    int u = __ldg(&src[ec]);
    int v = __ldg(&dst[ec]);
    edge_step(u, v, q, valid, fs, fd, at, out, den);
}

// ---------------- output head + fused BN stats ----------------
__global__ void head_kernel(const float* __restrict__ A, const float* __restrict__ B,
                            const float* __restrict__ s3, const float* __restrict__ s4,
                            const float* __restrict__ Wout, const float* __restrict__ bout,
                            float* __restrict__ y, int nu) {
    __shared__ float Wsh[32 * 65];
    __shared__ float ssum[32], ssq[32];
    int tid = threadIdx.x;
    for (int i = tid; i < 32 * 64; i += blockDim.x)
        Wsh[(i >> 6) * 65 + (i & 63)] = Wout[i];
    if (tid < 32) { ssum[tid] = 0.f; ssq[tid] = 0.f; }
    __syncthreads();
    int warp = tid >> 5, lane = tid & 31;
    int row = blockIdx.x * 8 + warp;
    if (row < nu) {
        float sa = s3[row]; sa = (sa > 0.f) ? (1.0f / sa) : 0.0f;
        float sb = s4[row]; sb = (sb > 0.f) ? (1.0f / sb) : 0.0f;
        float av = A[row * 32 + lane] * sa;
        float bv = B[row * 32 + lane] * sb;
        float acc = bout[lane];
#pragma unroll
        for (int k = 0; k < 32; ++k) {
            float ak = __shfl_sync(0xffffffffu, av, k);
            float bk = __shfl_sync(0xffffffffu, bv, k);
            acc += ak * Wsh[lane * 65 + k] + bk * Wsh[lane * 65 + 32 + k];
        }
        y[row * 32 + lane] = acc;
        atomicAdd(&ssum[lane], acc);
        atomicAdd(&ssq[lane], acc * acc);
    }
    __syncthreads();
    if (tid < 32) {
        atomicAdd(&g_stats[tid], ssum[tid]);
        atomicAdd(&g_stats[32 + tid], ssq[tid]);
    }
}

// ---------------- finalize: BN + LeakyReLU(0.01) ----------------
__global__ void finalize_kernel(float* __restrict__ y, const float* __restrict__ gamma,
                                const float* __restrict__ beta, int nu) {
    int i = blockIdx.x * blockDim.x + threadIdx.x;
    if (i >= nu * 32) return;
    int c = i & 31;
    float inv_n = 1.0f / (float)nu;
    float mean = g_stats[c] * inv_n;
    float var = g_stats[32 + c] * inv_n - mean * mean;
    float v = (y[i] - mean) * rsqrtf(var + 1e-5f) * gamma[c] + beta[c];
    y[i] = (v > 0.f) ? v : 0.01f * v;
}

// ---------------- host launch ----------------
extern "C" void kernel_launch(void* const* d_in, const int* in_sizes, int n_in,
                              void* d_out, int out_size) {
    const float* user = (const float*)d_in[0];
    const float* item = (const float*)d_in[1];
    const int* rate_src  = (const int*)d_in[2];
    const int* rate_dst  = (const int*)d_in[3];
    const int* trust_src = (const int*)d_in[4];
    const int* trust_dst = (const int*)d_in[5];
    const float* p[20];
    for (int i = 0; i < 20; ++i) p[i] = (const float*)d_in[6 + i];
    const float* Wout  = (const float*)d_in[26];
    const float* bout  = (const float*)d_in[27];
    const float* gamma = (const float*)d_in[28];
    const float* beta  = (const float*)d_in[29];

    int nu = in_sizes[0] / EDIM;
    int ni = in_sizes[1] / EDIM;
    int ne_rate  = in_sizes[2];
    int ne_trust = in_sizes[4];
    float* y = (float*)d_out;

    float *U0, *U1, *U2, *U3, *I0, *I1, *P1, *P2, *H1, *H2, *A, *B, *S1, *S2, *S3, *S4;
    cudaGetSymbolAddress((void**)&U0, g_U0);
    cudaGetSymbolAddress((void**)&U1, g_U1);
    cudaGetSymbolAddress((void**)&U2, g_U2);
    cudaGetSymbolAddress((void**)&U3, g_U3);
    cudaGetSymbolAddress((void**)&I0, g_I0);
    cudaGetSymbolAddress((void**)&I1, g_I1);
    cudaGetSymbolAddress((void**)&P1, g_P1);
    cudaGetSymbolAddress((void**)&P2, g_P2);
    cudaGetSymbolAddress((void**)&H1, g_H1);
    cudaGetSymbolAddress((void**)&H2, g_H2);
    cudaGetSymbolAddress((void**)&A,  g_A);
    cudaGetSymbolAddress((void**)&B,  g_B);
    cudaGetSymbolAddress((void**)&S1, g_S1);
    cudaGetSymbolAddress((void**)&S2, g_S2);
    cudaGetSymbolAddress((void**)&S3, g_S3);
    cudaGetSymbolAddress((void**)&S4, g_S4);

    const int T = 256;
    int gu = (nu + 7) / 8;
    int gi = (ni + 7) / 8;
    int gb_rate  = (ne_rate  * 8 + T - 1) / T;
    int gb_trust = (ne_trust * 8 + T - 1) / T;

    zero_all_kernel<<<2048, T>>>(nu, ni);

    // all user projections in one pass, all item projections in one pass
    proj4_kernel<<<gu, T>>>(user, p[0], p[1], p[7], p[8], p[12], p[13], p[17], p[18],
                            U0, U1, U2, U3, nu);
    proj2_kernel<<<gi, T>>>(item, p[2], p[3], p[5], p[6], I0, I1, ni);

    // layer 1 fused edge pass (rate + rated-by share the edge list)
    edge_l1_kernel<<<gb_rate, T>>>(rate_src, rate_dst,
                                   (const float4*)U0, (const float4*)I0, (const float4*)p[4], H1, S1,
                                   (const float4*)I1, (const float4*)U1, (const float4*)p[9], H2, S2,
                                   ne_rate);

    // layer-2 src projections (normalization folded via S1/S2), both in one grid
    projHH_kernel<<<gi + gu, T>>>(H1, S1, p[10], p[11], P1, ni, gi,
                                  H2, S2, p[15], p[16], P2, nu);

    // layer-2 dual edge pass
    edge_l2_kernel<<<gb_rate + gb_trust, T>>>(
        rate_dst, rate_src, (const float4*)P1, (const float4*)U2, (const float4*)p[14], A, S3,
        ne_rate, gb_rate,
        trust_src, trust_dst, (const float4*)P2, (const float4*)U3, (const float4*)p[19], B, S4,
        ne_trust);

    // head (+fused BN stats) + finalize
    head_kernel<<<gu, T>>>(A, B, S3, S4, Wout, bout, y, nu);
    finalize_kernel<<<(nu * EDIM + T - 1) / T, T>>>(y, gamma, beta, nu);
}